// round 2
// baseline (speedup 1.0000x reference)
#include <cuda_runtime.h>
#include <math.h>
#include <float.h>

#define NB      64
#define TOKENS  784
#define DIM     768
#define FH      28
#define IMG     448
#define TOPK    8
#define PATCH   16

// Scratch (no allocations allowed in kernel_launch)
__device__ float g_dist[NB * TOKENS];
__device__ int   g_box[NB][4];   // x0, x1, y0, y1

// ---------------------------------------------------------------------------
// Kernel 1: per-token ranking score = dot(g, l) / ||l||   (g-norm is a
// positive per-batch constant -> ordering identical to cosine similarity)
// grid (64, 8) x 256 threads: block (b,s) handles 98 token rows, one row per
// warp iteration. Streams 154 MB of x from HBM.
// ---------------------------------------------------------------------------
__global__ void sim_kernel(const float* __restrict__ x) {
    int b = blockIdx.x;
    int s = blockIdx.y;                       // 0..7 -> rows [s*98, s*98+98)
    const float* xb = x + (size_t)b * 785 * DIM;

    __shared__ float4 g_sh[DIM / 4];          // CLS token, 3 KB
    int tid = threadIdx.x;
    if (tid < DIM / 4) g_sh[tid] = ((const float4*)xb)[tid];
    __syncthreads();

    int warp = tid >> 5, lane = tid & 31;
    int r0 = s * 98;
    for (int r = r0 + warp; r < r0 + 98; r += 8) {
        const float4* lv = (const float4*)(xb + (size_t)(1 + r) * DIM);
        float dot = 0.f, nrm = 0.f;
#pragma unroll
        for (int j = 0; j < 6; ++j) {         // 6*32*4 = 768 elems
            float4 l = lv[lane + 32 * j];
            float4 g = g_sh[lane + 32 * j];
            dot += l.x * g.x + l.y * g.y + l.z * g.z + l.w * g.w;
            nrm += l.x * l.x + l.y * l.y + l.z * l.z + l.w * l.w;
        }
#pragma unroll
        for (int off = 16; off; off >>= 1) {
            dot += __shfl_xor_sync(0xffffffffu, dot, off);
            nrm += __shfl_xor_sync(0xffffffffu, nrm, off);
        }
        if (lane == 0) {
            float ln = fmaxf(sqrtf(nrm), 1e-8f);
            g_dist[b * TOKENS + r] = dot / ln;
        }
    }
}

// ---------------------------------------------------------------------------
// Kernel 2: top-8 argmax rounds (stable: ties -> lower index, matching
// jax.lax.top_k), then bounding box. One warp per batch.
// ---------------------------------------------------------------------------
__global__ void topk_kernel() {
    int b = blockIdx.x;
    int lane = threadIdx.x;                   // 32 threads
    __shared__ float dist[TOKENS];
    for (int i = lane; i < TOKENS; i += 32) dist[i] = g_dist[b * TOKENS + i];
    __syncwarp();

    int minx = FH, maxx = -1, miny = FH, maxy = -1;
#pragma unroll 1
    for (int k = 0; k < TOPK; ++k) {
        float best = -FLT_MAX; int bi = TOKENS;
        for (int i = lane; i < TOKENS; i += 32) {
            float v = dist[i];
            if (v > best) { best = v; bi = i; }   // strict > keeps lowest idx
        }
#pragma unroll
        for (int off = 16; off; off >>= 1) {
            float ov = __shfl_xor_sync(0xffffffffu, best, off);
            int   oi = __shfl_xor_sync(0xffffffffu, bi,   off);
            if (ov > best || (ov == best && oi < bi)) { best = ov; bi = oi; }
        }
        if (lane == 0) dist[bi] = -FLT_MAX;
        __syncwarp();
        int ix = bi / FH, iy = bi % FH;
        minx = min(minx, ix); maxx = max(maxx, ix);
        miny = min(miny, iy); maxy = max(maxy, iy);
    }
    if (lane == 0) {
        int x_i = minx * PATCH, x_f = maxx * PATCH;
        int y_i = miny * PATCH, y_f = maxy * PATCH;
        int x0 = max(x_i, 0);
        int y0 = max(y_i, 0);
        int x1 = min(max(x_f, x_i + PATCH), IMG);
        int y1 = min(max(y_f, y_i + PATCH), IMG);
        g_box[b][0] = x0; g_box[b][1] = x1;
        g_box[b][2] = y0; g_box[b][3] = y1;
    }
}

// ---------------------------------------------------------------------------
// Kernel 3: bilinear crop-resize, align_corners=True, exactly matching the
// reference index/weight formulas. One thread -> 4 consecutive output pixels
// (float4 store). Dominant kernel: ~154 MB write + <=154 MB gather reads.
// ---------------------------------------------------------------------------
__global__ void resize_kernel(const float* __restrict__ images,
                              float* __restrict__ out) {
    int gid = blockIdx.x * blockDim.x + threadIdx.x;
    int q = gid;
    int txq = q % (IMG / 4); q /= (IMG / 4);
    int ty  = q % IMG;       q /= IMG;
    int c   = q % 3;
    int b   = q / 3;
    if (b >= NB) return;

    int4 bx = *(const int4*)&g_box[b][0];
    int x0 = bx.x, x1 = bx.y, y0 = bx.z, y1 = bx.w;

    const float scale = 1.0f / (float)(IMG - 1);
    float h = (float)(x1 - x0), w = (float)(y1 - y0);

    float sy  = (float)x0 + (float)ty * (h - 1.0f) * scale;
    int   ylo = (int)floorf(sy);
    int   yhi = min(ylo + 1, x1 - 1);
    float wy  = sy - (float)ylo;

    const float* src = images + (((size_t)b * 3 + c) * IMG) * IMG;
    const float* row0 = src + (size_t)ylo * IMG;
    const float* row1 = src + (size_t)yhi * IMG;

    float wstep = (w - 1.0f) * scale;
    float4 res;
    float* rp = (float*)&res;
#pragma unroll
    for (int k = 0; k < 4; ++k) {
        int tx = txq * 4 + k;
        float sx  = (float)y0 + (float)tx * wstep;
        int   xlo = (int)floorf(sx);
        int   xhi = min(xlo + 1, y1 - 1);
        float wx  = sx - (float)xlo;
        float a  = __ldg(row0 + xlo);
        float bb = __ldg(row0 + xhi);
        float cc = __ldg(row1 + xlo);
        float dd = __ldg(row1 + xhi);
        rp[k] = (1.f - wy) * (1.f - wx) * a
              + (1.f - wy) * wx         * bb
              + wy         * (1.f - wx) * cc
              + wy         * wx         * dd;
    }
    ((float4*)out)[gid] = res;
}

// ---------------------------------------------------------------------------
extern "C" void kernel_launch(void* const* d_in, const int* in_sizes, int n_in,
                              void* d_out, int out_size) {
    const float* x      = (const float*)d_in[0];
    const float* images = (const float*)d_in[1];
    // Defensive: identify tensors by element count (x: 64*785*768, images: 64*3*448*448)
    const int X_ELEMS   = NB * 785 * DIM;
    if (n_in >= 2 && in_sizes[0] != X_ELEMS) {
        x      = (const float*)d_in[1];
        images = (const float*)d_in[0];
    }
    float* out = (float*)d_out;

    dim3 g1(NB, 8);
    sim_kernel<<<g1, 256>>>(x);
    topk_kernel<<<NB, 32>>>();
    // total outputs / 4 per thread: 64*3*448*448/4 = 9,633,792 threads
    resize_kernel<<<(NB * 3 * IMG * (IMG / 4)) / 256, 256>>>(images, out);
}